// round 10
// baseline (speedup 1.0000x reference)
#include <cuda_runtime.h>
#include <cuda_bf16.h>
#include <cuda_fp8.h>
#include <cstdint>
#include <cmath>

#define NG    8192
#define BGRP  16
#define GS    512
#define DIM   768

// fp8 tiles: CTA 128x128, TBK = 128 fp8 elems (128 bytes), warp tile 64x32
#define TBK8 128
#define NSTAGE 3
#define STAGE_BYTES (128 * TBK8)                    // 16384 per operand per stage
#define SMEM_BYTES (NSTAGE * 2 * STAGE_BYTES)       // 98304

// scale constants
#define WSCALE   64.0f     // weights stored x64
#define PSCALE   128.0f    // probabilities stored x128
#define DSCALE   32.0f     // DYN stored x32

// ---------------- scratch (device globals; no allocs allowed) ----------------
__device__ uint8_t       g_xq [NG * DIM];          // fp8(x)
__device__ uint8_t       g_Wq8[DIM * DIM];         // fp8(64*W)
__device__ uint8_t       g_Wk8[DIM * DIM];
__device__ uint8_t       g_Wv8[DIM * DIM];
__device__ uint8_t       g_Wo8[DIM * DIM];
__device__ uint8_t       g_Q  [NG * DIM];          // fp8(q)
__device__ uint8_t       g_K  [NG * DIM];          // fp8(k)
__device__ uint8_t       g_VT [DIM * NG];          // fp8(v) transposed [d, gene]
__device__ __nv_bfloat16 g_Sb [BGRP * GS * GS];    // raw scores bf16
__device__ uint8_t       g_P  [BGRP * GS * GS];    // fp8(128*p)
__device__ uint8_t       g_DYN[NG * DIM];          // fp8(32*dyn)

// ---------------- helpers ----------------
__device__ __forceinline__ unsigned sptr(const void* p) {
    return (unsigned)__cvta_generic_to_shared(p);
}
__device__ __forceinline__ void cpasync16(unsigned s, const void* g) {
    asm volatile("cp.async.cg.shared.global [%0], [%1], 16;\n" :: "r"(s), "l"(g));
}
__device__ __forceinline__ void cp_commit() {
    asm volatile("cp.async.commit_group;\n" ::: "memory");
}
__device__ __forceinline__ void cp_wait2() {
    asm volatile("cp.async.wait_group 2;\n" ::: "memory");
}
__device__ __forceinline__ void ldsm4(unsigned& r0, unsigned& r1, unsigned& r2, unsigned& r3, unsigned a) {
    asm volatile("ldmatrix.sync.aligned.m8n8.x4.shared.b16 {%0,%1,%2,%3}, [%4];\n"
                 : "=r"(r0), "=r"(r1), "=r"(r2), "=r"(r3) : "r"(a));
}
__device__ __forceinline__ void mma8(float* d, const unsigned* a, const unsigned* b) {
    asm volatile(
        "mma.sync.aligned.m16n8k32.row.col.f32.e4m3.e4m3.f32 "
        "{%0,%1,%2,%3}, {%4,%5,%6,%7}, {%8,%9}, {%0,%1,%2,%3};\n"
        : "+f"(d[0]), "+f"(d[1]), "+f"(d[2]), "+f"(d[3])
        : "r"(a[0]), "r"(a[1]), "r"(a[2]), "r"(a[3]), "r"(b[0]), "r"(b[1]));
}
__device__ __forceinline__ unsigned short f2e4m3x2(float lo, float hi) {
    return (unsigned short)__nv_cvt_float2_to_fp8x2(make_float2(lo, hi),
                                                    __NV_SATFINITE, __NV_E4M3);
}

// ---- cp.async tile issue: both operands NT (k-contiguous, 128-byte rows) ----
__device__ __forceinline__ void issue_tile8(
    const uint8_t* __restrict__ A, const uint8_t* __restrict__ B,
    uint8_t* As, uint8_t* Bs,
    int row0, int col0, int lda, int ldb, int kt, int tid)
{
#pragma unroll
    for (int i = 0; i < 4; i++) {
        int lin = tid + i * 256;
        int r = lin >> 3, c = lin & 7;
        cpasync16(sptr(As + r * TBK8 + ((c ^ (r & 7)) << 4)),
                  A + (long)(row0 + r) * lda + kt * TBK8 + c * 16);
    }
#pragma unroll
    for (int i = 0; i < 4; i++) {
        int lin = tid + i * 256;
        int r = lin >> 3, c = lin & 7;
        cpasync16(sptr(Bs + r * TBK8 + ((c ^ (r & 7)) << 4)),
                  B + (long)(col0 + r) * ldb + kt * TBK8 + c * 16);
    }
}

// ---------------------------------------------------------------------------
// FP8 e4m3 tensor-core GEMM body (NT): C[M,N] = A[M,K] @ B[N,K]^T
// acc = sum over K of fp8 products (fp32 accum). Epilogues:
// MODE 0: fp8  C = acc*escale + bias[col]       (Q, K projections; escale=1/64)
// MODE 4: fp8  C = acc*escale + bias[row]       (VT; escale=1/64)
// MODE 1: bf16 C = acc                          (raw scores)
// MODE 2: fp8  C = acc*escale                   (PV -> DYN'; escale=1/4)
// MODE 3: fp32 C = X + beta[0]*(acc*escale + bias[col])  (out-proj; escale=1/2048)
// 128x128xTBK8 tiles, 256 threads (8 warps 2x4), warp tile 64x32,
// 3-stage cp.async pipeline, swizzled smem, ldmatrix(b16-on-fp8) + mma.m16n8k32.
// ---------------------------------------------------------------------------
template<int MODE>
__device__ __forceinline__ void gemm_body8(
    const uint8_t* __restrict__ A, const uint8_t* __restrict__ B,
    const float* __restrict__ bias, void* __restrict__ Cv,
    int K, int lda, int ldb, int ldc,
    const float* __restrict__ X, const float* __restrict__ beta, float escale,
    char* dsm, int row0, int col0)
{
    uint8_t* As = reinterpret_cast<uint8_t*>(dsm);
    uint8_t* Bs = As + NSTAGE * STAGE_BYTES;

    const int tid  = threadIdx.x;
    const int lane = tid & 31;
    const int wid  = tid >> 5;
    const int wm   = (wid & 1) * 64;
    const int wn   = (wid >> 1) * 32;
    const int sub  = lane >> 3;              // ldsm sub-matrix id 0..3
    const int srow = (lane & 7) + ((sub & 1) << 3);   // 0..15 row within 16-row frag
    const int skc  = sub >> 1;               // 16B chunk parity (k 0-15 vs 16-31)

    float acc[4][4][4];
#pragma unroll
    for (int i = 0; i < 4; i++)
#pragma unroll
        for (int j = 0; j < 4; j++)
#pragma unroll
            for (int k = 0; k < 4; k++) acc[i][j][k] = 0.f;

    const int ntiles = K / TBK8;

    issue_tile8(A, B, As, Bs, row0, col0, lda, ldb, 0, tid);
    cp_commit();
    issue_tile8(A, B, As + STAGE_BYTES, Bs + STAGE_BYTES, row0, col0, lda, ldb, 1, tid);
    cp_commit();

    for (int kt = 0; kt < ntiles; kt++) {
        const int stg = kt % NSTAGE;
        if (kt + 2 < ntiles) {
            const int ps = (kt + 2) % NSTAGE;
            issue_tile8(A, B, As + ps * STAGE_BYTES, Bs + ps * STAGE_BYTES,
                        row0, col0, lda, ldb, kt + 2, tid);
        }
        cp_commit();
        cp_wait2();
        __syncthreads();

        const uint8_t* Asb = As + stg * STAGE_BYTES;
        const uint8_t* Bsb = Bs + stg * STAGE_BYTES;

#pragma unroll
        for (int ks = 0; ks < 4; ks++) {     // four k32 steps per TBK8=128
            unsigned aF[4][4], bF[4][2];
#pragma unroll
            for (int mi = 0; mi < 4; mi++) {
                int r = wm + mi * 16 + srow;
                int c = ks * 2 + skc;
                ldsm4(aF[mi][0], aF[mi][1], aF[mi][2], aF[mi][3],
                      sptr(Asb + r * TBK8 + ((c ^ (r & 7)) << 4)));
            }
#pragma unroll
            for (int nt = 0; nt < 2; nt++) {
                int r = wn + nt * 16 + srow;
                int c = ks * 2 + skc;
                unsigned r0, r1, r2, r3;
                ldsm4(r0, r1, r2, r3,
                      sptr(Bsb + r * TBK8 + ((c ^ (r & 7)) << 4)));
                bF[nt * 2 + 0][0] = r0; bF[nt * 2 + 0][1] = r2;
                bF[nt * 2 + 1][0] = r1; bF[nt * 2 + 1][1] = r3;
            }
#pragma unroll
            for (int mi = 0; mi < 4; mi++)
#pragma unroll
                for (int nj = 0; nj < 4; nj++)
                    mma8(acc[mi][nj], aF[mi], bF[nj]);
        }
        __syncthreads();
    }

    // ---------------- epilogue ----------------
    const int rg = lane >> 2;
    const int t  = lane & 3;
    float betav = 0.f;
    if (MODE == 3) betav = beta[0];

#pragma unroll
    for (int mi = 0; mi < 4; mi++) {
#pragma unroll
        for (int nj = 0; nj < 4; nj++) {
            const int r = row0 + wm + mi * 16 + rg;
            const int c = col0 + wn + nj * 8 + t * 2;
            const float d0 = acc[mi][nj][0];
            const float d1 = acc[mi][nj][1];
            const float d2 = acc[mi][nj][2];
            const float d3 = acc[mi][nj][3];

            if (MODE == 0) {
                uint8_t* C = reinterpret_cast<uint8_t*>(Cv);
                const float2 bb = *reinterpret_cast<const float2*>(bias + c);
                *reinterpret_cast<unsigned short*>(C + (long)r * ldc + c) =
                    f2e4m3x2(d0 * escale + bb.x, d1 * escale + bb.y);
                *reinterpret_cast<unsigned short*>(C + (long)(r + 8) * ldc + c) =
                    f2e4m3x2(d2 * escale + bb.x, d3 * escale + bb.y);
            } else if (MODE == 4) {
                uint8_t* C = reinterpret_cast<uint8_t*>(Cv);
                const float b0 = bias[r];
                const float b1 = bias[r + 8];
                *reinterpret_cast<unsigned short*>(C + (long)r * ldc + c) =
                    f2e4m3x2(d0 * escale + b0, d1 * escale + b0);
                *reinterpret_cast<unsigned short*>(C + (long)(r + 8) * ldc + c) =
                    f2e4m3x2(d2 * escale + b1, d3 * escale + b1);
            } else if (MODE == 1) {
                __nv_bfloat16* C = reinterpret_cast<__nv_bfloat16*>(Cv);
                *reinterpret_cast<__nv_bfloat162*>(C + (long)r * ldc + c) =
                    __floats2bfloat162_rn(d0, d1);
                *reinterpret_cast<__nv_bfloat162*>(C + (long)(r + 8) * ldc + c) =
                    __floats2bfloat162_rn(d2, d3);
            } else if (MODE == 2) {
                uint8_t* C = reinterpret_cast<uint8_t*>(Cv);
                *reinterpret_cast<unsigned short*>(C + (long)r * ldc + c) =
                    f2e4m3x2(d0 * escale, d1 * escale);
                *reinterpret_cast<unsigned short*>(C + (long)(r + 8) * ldc + c) =
                    f2e4m3x2(d2 * escale, d3 * escale);
            } else {
                float* C = reinterpret_cast<float*>(Cv);
                const float2 bb = *reinterpret_cast<const float2*>(bias + c);
                const float2 x0 = *reinterpret_cast<const float2*>(X + (long)r * ldc + c);
                const float2 x1 = *reinterpret_cast<const float2*>(X + (long)(r + 8) * ldc + c);
                *reinterpret_cast<float2*>(C + (long)r * ldc + c) =
                    make_float2(x0.x + betav * (d0 * escale + bb.x),
                                x0.y + betav * (d1 * escale + bb.y));
                *reinterpret_cast<float2*>(C + (long)(r + 8) * ldc + c) =
                    make_float2(x1.x + betav * (d2 * escale + bb.x),
                                x1.y + betav * (d3 * escale + bb.y));
            }
        }
    }
}

// ---------------- Q/K fused: grid.z in {0,1} selects W/bias/C ----------------
__global__ __launch_bounds__(256, 2)
void hgemm_qk(const uint8_t* __restrict__ A,
              const uint8_t* __restrict__ W0, const uint8_t* __restrict__ W1,
              const float* __restrict__ b0, const float* __restrict__ b1,
              uint8_t* __restrict__ C0, uint8_t* __restrict__ C1)
{
    extern __shared__ char dsm[];
    const int z = blockIdx.z;
    const uint8_t* W  = (z == 0) ? W0 : W1;
    const float* bias = (z == 0) ? b0 : b1;
    uint8_t* C        = (z == 0) ? C0 : C1;
    gemm_body8<0>(A, W, bias, C, DIM, DIM, DIM, DIM, nullptr, nullptr, 1.0f / WSCALE,
                  dsm, blockIdx.y * 128, blockIdx.x * 128);
}

// ---------------- generic batched fp8 GEMM (z = group) ----------------
template<int MODE>
__global__ __launch_bounds__(256, 2)
void hgemm8(const uint8_t* __restrict__ A, const uint8_t* __restrict__ B,
            const float* __restrict__ bias, void* __restrict__ Cv,
            int K, int lda, int ldb, int ldc,
            long sA, long sB, long sC, float escale,
            const float* __restrict__ X, const float* __restrict__ beta)
{
    extern __shared__ char dsm[];
    const int bz = blockIdx.z;
    void* C;
    if (MODE == 1)      C = (void*)((__nv_bfloat16*)Cv + bz * sC);
    else if (MODE == 3) C = (void*)((float*)Cv + bz * sC);
    else                C = (void*)((uint8_t*)Cv + bz * sC);
    gemm_body8<MODE>(A + bz * sA, B + bz * sB, bias, C,
                     K, lda, ldb, ldc, X, beta, escale,
                     dsm, blockIdx.y * 128, blockIdx.x * 128);
}

// ---------------- merged fp32 -> fp8 converts (x + 4 weights x64) ----------------
__global__ __launch_bounds__(256)
void conv_all8(const float* __restrict__ x,
               const float* __restrict__ wq, const float* __restrict__ wk,
               const float* __restrict__ wv, const float* __restrict__ wo,
               uint8_t* __restrict__ xq,
               uint8_t* __restrict__ wq8, uint8_t* __restrict__ wk8,
               uint8_t* __restrict__ wv8, uint8_t* __restrict__ wo8)
{
    const long NX = (long)NG * DIM;
    const long W  = (long)DIM * DIM;
    long i = ((long)blockIdx.x * 256 + threadIdx.x) * 4;
    if (i >= NX + 4 * W) return;
    const float* src;
    uint8_t* dst;
    long off;
    float s;
    if (i < NX) { src = x; dst = xq; off = i; s = 1.0f; }
    else {
        long j = i - NX;
        int w = (int)(j / W);
        off = j - (long)w * W;
        src = (w == 0) ? wq : (w == 1) ? wk : (w == 2) ? wv : wo;
        dst = (w == 0) ? wq8 : (w == 1) ? wk8 : (w == 2) ? wv8 : wo8;
        s = WSCALE;
    }
    float4 v = *reinterpret_cast<const float4*>(src + off);
    unsigned short h0 = f2e4m3x2(v.x * s, v.y * s);
    unsigned short h1 = f2e4m3x2(v.z * s, v.w * s);
    *reinterpret_cast<unsigned*>(dst + off) = (unsigned)h0 | ((unsigned)h1 << 16);
}

// ---------------- masked softmax: bf16 raw scores -> fp8(128*p) ----------------
// warp-per-row, 8 rows per 256-thread CTA, 16 elems/lane.
__global__ __launch_bounds__(256)
void softmax_rows(const __nv_bfloat16* __restrict__ S, uint8_t* __restrict__ P, float scale)
{
    const int row  = blockIdx.x * 8 + (threadIdx.x >> 5);
    const int lane = threadIdx.x & 31;
    const int grp  = row >> 9;
    const int r    = row & 511;
    const __nv_bfloat16* p = S + ((long)grp << 18) + ((long)r << 9);
    uint8_t* q = P + ((long)grp << 18) + ((long)r << 9);

    float v[16];
    float mx = -INFINITY;
#pragma unroll
    for (int i = 0; i < 2; i++) {
        const int col = i * 256 + lane * 8;
        uint4 raw = *reinterpret_cast<const uint4*>(p + col);
        const unsigned w[4] = {raw.x, raw.y, raw.z, raw.w};
#pragma unroll
        for (int j = 0; j < 4; j++) {
            float2 f2 = __bfloat1622float2(*reinterpret_cast<const __nv_bfloat162*>(&w[j]));
            float a = f2.x * scale, b = f2.y * scale;
            if (col + 2 * j + 0 == r) a = -INFINITY;
            if (col + 2 * j + 1 == r) b = -INFINITY;
            v[i * 8 + 2 * j + 0] = a;
            v[i * 8 + 2 * j + 1] = b;
            mx = fmaxf(mx, fmaxf(a, b));
        }
    }
#pragma unroll
    for (int o = 16; o; o >>= 1) mx = fmaxf(mx, __shfl_xor_sync(0xffffffffu, mx, o));

    float sum = 0.f;
#pragma unroll
    for (int i = 0; i < 16; i++) { v[i] = __expf(v[i] - mx); sum += v[i]; }
#pragma unroll
    for (int o = 16; o; o >>= 1) sum += __shfl_xor_sync(0xffffffffu, sum, o);
    const float ps = PSCALE / sum;

#pragma unroll
    for (int i = 0; i < 2; i++) {
        const int col = i * 256 + lane * 8;
        unsigned short h0 = f2e4m3x2(v[i * 8 + 0] * ps, v[i * 8 + 1] * ps);
        unsigned short h1 = f2e4m3x2(v[i * 8 + 2] * ps, v[i * 8 + 3] * ps);
        unsigned short h2 = f2e4m3x2(v[i * 8 + 4] * ps, v[i * 8 + 5] * ps);
        unsigned short h3 = f2e4m3x2(v[i * 8 + 6] * ps, v[i * 8 + 7] * ps);
        uint2 out;
        out.x = (unsigned)h0 | ((unsigned)h1 << 16);
        out.y = (unsigned)h2 | ((unsigned)h3 << 16);
        *reinterpret_cast<uint2*>(q + col) = out;
    }
}

// ---------------------------------------------------------------------------
// Launcher. Inputs: x, batch(unused), Wq,bq, Wk,bk, Wv,bv, Wo,bo, beta.
// ---------------------------------------------------------------------------
extern "C" void kernel_launch(void* const* d_in, const int* in_sizes, int n_in,
                              void* d_out, int out_size)
{
    (void)in_sizes; (void)n_in; (void)out_size;
    const float* x    = (const float*)d_in[0];
    const float* Wq   = (const float*)d_in[2];
    const float* bq   = (const float*)d_in[3];
    const float* Wk   = (const float*)d_in[4];
    const float* bk   = (const float*)d_in[5];
    const float* Wv   = (const float*)d_in[6];
    const float* bv   = (const float*)d_in[7];
    const float* Wo   = (const float*)d_in[8];
    const float* bo   = (const float*)d_in[9];
    const float* beta = (const float*)d_in[10];
    float* out = (float*)d_out;

    uint8_t *xq, *Wq8, *Wk8, *Wv8, *Wo8, *Q, *K, *VT, *P, *DYN;
    __nv_bfloat16 *Sb;
    cudaGetSymbolAddress((void**)&xq,  g_xq);
    cudaGetSymbolAddress((void**)&Wq8, g_Wq8);
    cudaGetSymbolAddress((void**)&Wk8, g_Wk8);
    cudaGetSymbolAddress((void**)&Wv8, g_Wv8);
    cudaGetSymbolAddress((void**)&Wo8, g_Wo8);
    cudaGetSymbolAddress((void**)&Q,   g_Q);
    cudaGetSymbolAddress((void**)&K,   g_K);
    cudaGetSymbolAddress((void**)&VT,  g_VT);
    cudaGetSymbolAddress((void**)&Sb,  g_Sb);
    cudaGetSymbolAddress((void**)&P,   g_P);
    cudaGetSymbolAddress((void**)&DYN, g_DYN);

    static bool attr_done = false;
    if (!attr_done) {
        cudaFuncSetAttribute(hgemm_qk,  cudaFuncAttributeMaxDynamicSharedMemorySize, SMEM_BYTES);
        cudaFuncSetAttribute(hgemm8<1>, cudaFuncAttributeMaxDynamicSharedMemorySize, SMEM_BYTES);
        cudaFuncSetAttribute(hgemm8<2>, cudaFuncAttributeMaxDynamicSharedMemorySize, SMEM_BYTES);
        cudaFuncSetAttribute(hgemm8<3>, cudaFuncAttributeMaxDynamicSharedMemorySize, SMEM_BYTES);
        cudaFuncSetAttribute(hgemm8<4>, cudaFuncAttributeMaxDynamicSharedMemorySize, SMEM_BYTES);
        attr_done = true;
    }

    const float scale = 1.0f / sqrtf((float)DIM);
    const dim3 blk(256);

    // fp32 -> fp8 converts (one launch; weights x64)
    {
        long total4 = ((long)NG * DIM + 4L * DIM * DIM) / 4;
        int blocks = (int)((total4 + 255) / 256);
        conv_all8<<<blocks, 256>>>(x, Wq, Wk, Wv, Wo, xq, Wq8, Wk8, Wv8, Wo8);
    }

    // Q, K projections: fp8 [8192,768] @ [768,768]^T, acc/64 + bias -> fp8
    hgemm_qk<<<dim3(6, 64, 2), blk, SMEM_BYTES>>>(xq, Wq8, Wk8, bq, bk, Q, K);

    // VT = Wv @ x^T (+bv per row): [768, 8192] fp8 (V transposed)
    hgemm8<4><<<dim3(64, 6, 1), blk, SMEM_BYTES>>>(
        Wv8, xq, bv, VT, DIM, DIM, DIM, NG,
        0, 0, 0, 1.0f / WSCALE, nullptr, nullptr);

    // Scores: Sb_g = Q_g @ K_g^T raw (bf16 out), batched z=16
    hgemm8<1><<<dim3(4, 4, BGRP), blk, SMEM_BYTES>>>(
        Q, K, nullptr, Sb, DIM, DIM, DIM, GS,
        (long)GS * DIM, (long)GS * DIM, (long)GS * GS, 1.0f, nullptr, nullptr);

    // Masked softmax (scale folded): bf16 -> fp8(128*p)
    softmax_rows<<<NG / 8, 256>>>(Sb, P, scale);

    // DYN' = P' @ VT_g^T: [512, 768] per group, fp8(acc/4) = fp8(32*dyn)
    hgemm8<2><<<dim3(6, 4, BGRP), blk, SMEM_BYTES>>>(
        P, VT, nullptr, DYN, GS, GS, NG, DIM,
        (long)GS * GS, (long)GS, (long)GS * DIM, 0.25f, nullptr, nullptr);

    // out = x + beta*(acc/2048 + bo): fp32
    hgemm8<3><<<dim3(6, 64, 1), blk, SMEM_BYTES>>>(
        DYN, Wo8, bo, out, DIM, DIM, DIM, DIM,
        0, 0, 0, 1.0f / (WSCALE * DSCALE), x, beta);
}

// round 11
// speedup vs baseline: 1.1712x; 1.1712x over previous
#include <cuda_runtime.h>
#include <cuda_bf16.h>
#include <cstdint>
#include <cmath>

#define NG    8192
#define BGRP  16
#define GS    512
#define DIM   768

// tile sizes (R7 proven config)
#define TBM 128
#define TBN 128
#define TBK 64
#define NSTAGE 3
#define STAGE_ELEMS (TBM * TBK)                   // 8192 bf16 per operand per stage
#define SMEM_BYTES (NSTAGE * 2 * STAGE_ELEMS * 2) // 98304 bytes

// ---------------- scratch (device globals; no allocs allowed) ----------------
__device__ __nv_bfloat16 g_xb [NG * DIM];
__device__ __nv_bfloat16 g_Wqb[DIM * DIM];
__device__ __nv_bfloat16 g_Wkb[DIM * DIM];
__device__ __nv_bfloat16 g_Wvb[DIM * DIM];
__device__ __nv_bfloat16 g_Wob[DIM * DIM];
__device__ __nv_bfloat16 g_Q  [NG * DIM];
__device__ __nv_bfloat16 g_K  [NG * DIM];
__device__ __nv_bfloat16 g_V  [NG * DIM];
__device__ float         g_S  [BGRP * GS * GS];
__device__ __nv_bfloat16 g_P  [BGRP * GS * GS];
__device__ __nv_bfloat16 g_DYN[NG * DIM];

// ---------------- helpers ----------------
__device__ __forceinline__ unsigned sptr(const void* p) {
    return (unsigned)__cvta_generic_to_shared(p);
}
__device__ __forceinline__ void cpasync16(unsigned s, const void* g) {
    asm volatile("cp.async.cg.shared.global [%0], [%1], 16;\n" :: "r"(s), "l"(g));
}
__device__ __forceinline__ void cp_commit() {
    asm volatile("cp.async.commit_group;\n" ::: "memory");
}
__device__ __forceinline__ void cp_wait1() {
    asm volatile("cp.async.wait_group 1;\n" ::: "memory");
}
__device__ __forceinline__ void ldsm4(unsigned& r0, unsigned& r1, unsigned& r2, unsigned& r3, unsigned a) {
    asm volatile("ldmatrix.sync.aligned.m8n8.x4.shared.b16 {%0,%1,%2,%3}, [%4];\n"
                 : "=r"(r0), "=r"(r1), "=r"(r2), "=r"(r3) : "r"(a));
}
__device__ __forceinline__ void ldsm4t(unsigned& r0, unsigned& r1, unsigned& r2, unsigned& r3, unsigned a) {
    asm volatile("ldmatrix.sync.aligned.m8n8.x4.trans.shared.b16 {%0,%1,%2,%3}, [%4];\n"
                 : "=r"(r0), "=r"(r1), "=r"(r2), "=r"(r3) : "r"(a));
}
__device__ __forceinline__ void mma16816(float* d, const unsigned* a, const unsigned* b) {
    asm volatile(
        "mma.sync.aligned.m16n8k16.row.col.f32.bf16.bf16.f32 "
        "{%0,%1,%2,%3}, {%4,%5,%6,%7}, {%8,%9}, {%0,%1,%2,%3};\n"
        : "+f"(d[0]), "+f"(d[1]), "+f"(d[2]), "+f"(d[3])
        : "r"(a[0]), "r"(a[1]), "r"(a[2]), "r"(a[3]), "r"(b[0]), "r"(b[1]));
}

// ---- cp.async tile issue into stage buffers (BK=64 -> 128B rows, 8-way XOR swizzle) ----
template<bool TB>
__device__ __forceinline__ void issue_tile(
    const __nv_bfloat16* __restrict__ A, const __nv_bfloat16* __restrict__ B,
    __nv_bfloat16* As, __nv_bfloat16* Bs,
    int row0, int col0, int lda, int ldb, int kt, int tid)
{
#pragma unroll
    for (int i = 0; i < 4; i++) {
        int lin = tid + i * 256;
        int r = lin >> 3, c = lin & 7;
        const __nv_bfloat16* g = A + (long)(row0 + r) * lda + kt * TBK + c * 8;
        cpasync16(sptr(As + r * TBK + ((c ^ (r & 7)) << 3)), g);
    }
    if (!TB) {
#pragma unroll
        for (int i = 0; i < 4; i++) {
            int lin = tid + i * 256;
            int r = lin >> 3, c = lin & 7;
            const __nv_bfloat16* g = B + (long)(col0 + r) * ldb + kt * TBK + c * 8;
            cpasync16(sptr(Bs + r * TBK + ((c ^ (r & 7)) << 3)), g);
        }
    } else {
#pragma unroll
        for (int i = 0; i < 4; i++) {
            int lin = tid + i * 256;
            int r = lin >> 4, c = lin & 15;
            const __nv_bfloat16* g = B + (long)(kt * TBK + r) * ldb + col0 + c * 8;
            cpasync16(sptr(Bs + r * TBN + ((c ^ (r & 7)) << 3)), g);
        }
    }
}

// ---------------------------------------------------------------------------
// Core bf16 tensor-core GEMM body: C[M,N] = A[M,K] @ op(B)
//   TB=false: B is [N,K] row-major -> C = A @ B^T (NT)
//   TB=true : B is [K,N] row-major -> C = A @ B   (NN)
// MODE 0: bf16 C = acc + bias[col]
// MODE 1: fp32 C = acc                  (scores; scale folded into softmax)
// MODE 2: bf16 C = acc                  (PV)
// MODE 3: fp32 C = X + beta[0]*(acc + bias[col])
// 128x128x64 tiles, 256 threads (8 warps 2x4), warp tile 64x32,
// 3-stage cp.async pipeline with SINGLE barrier per iter (CUTLASS order:
// wait -> sync -> compute(kt) -> issue(kt+2) -> commit; issue target
// (kt+2)%3 == (kt-1)%3, a buffer all threads finished last iter).
// ---------------------------------------------------------------------------
template<int MODE, bool TB>
__device__ __forceinline__ void gemm_body(
    const __nv_bfloat16* __restrict__ A, const __nv_bfloat16* __restrict__ B,
    const float* __restrict__ bias, void* __restrict__ Cv,
    int K, int lda, int ldb, int ldc,
    const float* __restrict__ X, const float* __restrict__ beta,
    char* dsm, int row0, int col0)
{
    __nv_bfloat16* As = reinterpret_cast<__nv_bfloat16*>(dsm);
    __nv_bfloat16* Bs = As + NSTAGE * STAGE_ELEMS;

    const int tid  = threadIdx.x;
    const int lane = tid & 31;
    const int wid  = tid >> 5;
    const int wm   = (wid & 1) * 64;
    const int wn   = (wid >> 1) * 32;

    float acc[4][4][4];
#pragma unroll
    for (int i = 0; i < 4; i++)
#pragma unroll
        for (int j = 0; j < 4; j++)
#pragma unroll
            for (int k = 0; k < 4; k++) acc[i][j][k] = 0.f;

    const int ntiles = K / TBK;

    issue_tile<TB>(A, B, As, Bs, row0, col0, lda, ldb, 0, tid);
    cp_commit();
    issue_tile<TB>(A, B, As + STAGE_ELEMS, Bs + STAGE_ELEMS, row0, col0, lda, ldb, 1, tid);
    cp_commit();

    for (int kt = 0; kt < ntiles; kt++) {
        const int stg = kt % NSTAGE;
        cp_wait1();              // tile kt resident (<=1 pending group)
        __syncthreads();         // visibility of all threads' copies + buffer-reuse guard

        const __nv_bfloat16* Asb = As + stg * STAGE_ELEMS;
        const __nv_bfloat16* Bsb = Bs + stg * STAGE_ELEMS;

#pragma unroll
        for (int ks = 0; ks < 4; ks++) {          // four k16 steps per BK=64
            unsigned aF[4][4], bF[4][2];
#pragma unroll
            for (int mi = 0; mi < 4; mi++) {
                int r = wm + mi * 16 + (lane & 15);
                int c = ks * 2 + (lane >> 4);
                ldsm4(aF[mi][0], aF[mi][1], aF[mi][2], aF[mi][3],
                      sptr(Asb + r * TBK + ((c ^ (r & 7)) << 3)));
            }
            if (!TB) {
#pragma unroll
                for (int nt = 0; nt < 2; nt++) {
                    int r = wn + nt * 16 + (lane & 15);
                    int c = ks * 2 + (lane >> 4);
                    unsigned r0, r1, r2, r3;
                    ldsm4(r0, r1, r2, r3,
                          sptr(Bsb + r * TBK + ((c ^ (r & 7)) << 3)));
                    bF[nt * 2 + 0][0] = r0; bF[nt * 2 + 0][1] = r2;
                    bF[nt * 2 + 1][0] = r1; bF[nt * 2 + 1][1] = r3;
                }
            } else {
#pragma unroll
                for (int nt = 0; nt < 2; nt++) {
                    int r = ks * 16 + (lane & 15);
                    int c = (wn >> 3) + nt * 2 + (lane >> 4);
                    unsigned r0, r1, r2, r3;
                    ldsm4t(r0, r1, r2, r3,
                           sptr(Bsb + r * TBN + ((c ^ (r & 7)) << 3)));
                    bF[nt * 2 + 0][0] = r0; bF[nt * 2 + 0][1] = r1;
                    bF[nt * 2 + 1][0] = r2; bF[nt * 2 + 1][1] = r3;
                }
            }
#pragma unroll
            for (int mi = 0; mi < 4; mi++)
#pragma unroll
                for (int nj = 0; nj < 4; nj++)
                    mma16816(acc[mi][nj], aF[mi], bF[nj]);
        }

        // issue next tile into the buffer freed last iteration; commit keeps
        // group counting aligned even when nothing is issued (tail).
        if (kt + 2 < ntiles) {
            const int ps = (kt + 2) % NSTAGE;
            issue_tile<TB>(A, B, As + ps * STAGE_ELEMS, Bs + ps * STAGE_ELEMS,
                           row0, col0, lda, ldb, kt + 2, tid);
        }
        cp_commit();
    }

    // ---------------- epilogue ----------------
    const int rg = lane >> 2;
    const int t  = lane & 3;
    float betav = 0.f;
    if (MODE == 3) betav = beta[0];

#pragma unroll
    for (int mi = 0; mi < 4; mi++) {
#pragma unroll
        for (int nj = 0; nj < 4; nj++) {
            const int r = row0 + wm + mi * 16 + rg;
            const int c = col0 + wn + nj * 8 + t * 2;
            const float d0 = acc[mi][nj][0];
            const float d1 = acc[mi][nj][1];
            const float d2 = acc[mi][nj][2];
            const float d3 = acc[mi][nj][3];

            if (MODE == 0) {
                __nv_bfloat16* C = reinterpret_cast<__nv_bfloat16*>(Cv);
                const float2 bb = *reinterpret_cast<const float2*>(bias + c);
                *reinterpret_cast<__nv_bfloat162*>(C + (long)r * ldc + c) =
                    __floats2bfloat162_rn(d0 + bb.x, d1 + bb.y);
                *reinterpret_cast<__nv_bfloat162*>(C + (long)(r + 8) * ldc + c) =
                    __floats2bfloat162_rn(d2 + bb.x, d3 + bb.y);
            } else if (MODE == 1) {
                float* C = reinterpret_cast<float*>(Cv);
                *reinterpret_cast<float2*>(C + (long)r * ldc + c) = make_float2(d0, d1);
                *reinterpret_cast<float2*>(C + (long)(r + 8) * ldc + c) = make_float2(d2, d3);
            } else if (MODE == 2) {
                __nv_bfloat16* C = reinterpret_cast<__nv_bfloat16*>(Cv);
                *reinterpret_cast<__nv_bfloat162*>(C + (long)r * ldc + c) =
                    __floats2bfloat162_rn(d0, d1);
                *reinterpret_cast<__nv_bfloat162*>(C + (long)(r + 8) * ldc + c) =
                    __floats2bfloat162_rn(d2, d3);
            } else {
                float* C = reinterpret_cast<float*>(Cv);
                const float2 bb = *reinterpret_cast<const float2*>(bias + c);
                const float2 x0 = *reinterpret_cast<const float2*>(X + (long)r * ldc + c);
                const float2 x1 = *reinterpret_cast<const float2*>(X + (long)(r + 8) * ldc + c);
                *reinterpret_cast<float2*>(C + (long)r * ldc + c) =
                    make_float2(x0.x + betav * (d0 + bb.x), x0.y + betav * (d1 + bb.y));
                *reinterpret_cast<float2*>(C + (long)(r + 8) * ldc + c) =
                    make_float2(x1.x + betav * (d2 + bb.x), x1.y + betav * (d3 + bb.y));
            }
        }
    }
}

// ---------------- QKV fused: grid.z in {0,1,2} selects W/bias/C ----------------
__global__ __launch_bounds__(256, 2)
void hgemm_qkv(const __nv_bfloat16* __restrict__ A,
               const __nv_bfloat16* __restrict__ W0, const __nv_bfloat16* __restrict__ W1,
               const __nv_bfloat16* __restrict__ W2,
               const float* __restrict__ b0, const float* __restrict__ b1,
               const float* __restrict__ b2,
               __nv_bfloat16* __restrict__ C0, __nv_bfloat16* __restrict__ C1,
               __nv_bfloat16* __restrict__ C2)
{
    extern __shared__ char dsm[];
    const int z = blockIdx.z;
    const __nv_bfloat16* W = (z == 0) ? W0 : (z == 1) ? W1 : W2;
    const float* bias      = (z == 0) ? b0 : (z == 1) ? b1 : b2;
    __nv_bfloat16* C       = (z == 0) ? C0 : (z == 1) ? C1 : C2;
    gemm_body<0, false>(A, W, bias, C, DIM, DIM, DIM, DIM, nullptr, nullptr,
                        dsm, blockIdx.y * TBM, blockIdx.x * TBN);
}

// ---------------- generic batched GEMM (z = group) ----------------
template<int MODE, bool TB>
__global__ __launch_bounds__(256, 2)
void hgemm(const __nv_bfloat16* __restrict__ A, const __nv_bfloat16* __restrict__ B,
           const float* __restrict__ bias, void* __restrict__ Cv,
           int K, int lda, int ldb, int ldc,
           long sA, long sB, long sC,
           const float* __restrict__ X, const float* __restrict__ beta)
{
    extern __shared__ char dsm[];
    const int bz = blockIdx.z;
    void* C;
    if (MODE == 1 || MODE == 3) C = (void*)((float*)Cv + bz * sC);
    else                        C = (void*)((__nv_bfloat16*)Cv + bz * sC);
    gemm_body<MODE, TB>(A + bz * sA, B + bz * sB, bias, C,
                        K, lda, ldb, ldc, X, beta,
                        dsm, blockIdx.y * TBM, blockIdx.x * TBN);
}

// ---------------- merged fp32 -> bf16 converts ----------------
__global__ __launch_bounds__(256)
void conv_all(const float* __restrict__ x,
              const float* __restrict__ wq, const float* __restrict__ wk,
              const float* __restrict__ wv, const float* __restrict__ wo,
              __nv_bfloat16* __restrict__ xb,
              __nv_bfloat16* __restrict__ wqb, __nv_bfloat16* __restrict__ wkb,
              __nv_bfloat16* __restrict__ wvb, __nv_bfloat16* __restrict__ wob)
{
    const long NX = (long)NG * DIM;
    const long W  = (long)DIM * DIM;
    long i = ((long)blockIdx.x * 256 + threadIdx.x) * 4;
    if (i >= NX + 4 * W) return;
    const float* src;
    __nv_bfloat16* dst;
    long off;
    if (i < NX) { src = x; dst = xb; off = i; }
    else {
        long j = i - NX;
        int w = (int)(j / W);
        off = j - (long)w * W;
        src = (w == 0) ? wq : (w == 1) ? wk : (w == 2) ? wv : wo;
        dst = (w == 0) ? wqb : (w == 1) ? wkb : (w == 2) ? wvb : wob;
    }
    float4 v = *reinterpret_cast<const float4*>(src + off);
    *reinterpret_cast<__nv_bfloat162*>(dst + off)     = __floats2bfloat162_rn(v.x, v.y);
    *reinterpret_cast<__nv_bfloat162*>(dst + off + 2) = __floats2bfloat162_rn(v.z, v.w);
}

// ---------------- masked softmax (scale folded), warp-per-row ----------------
__global__ __launch_bounds__(256)
void softmax_rows(const float* __restrict__ S, __nv_bfloat16* __restrict__ P, float scale)
{
    const int row  = blockIdx.x * 8 + (threadIdx.x >> 5);
    const int lane = threadIdx.x & 31;
    const int grp  = row >> 9;
    const int r    = row & 511;
    const float* p = S + ((long)grp << 18) + ((long)r << 9);
    __nv_bfloat16* q = P + ((long)grp << 18) + ((long)r << 9);

    float v[16];
    float mx = -INFINITY;
#pragma unroll
    for (int i = 0; i < 4; i++) {
        const int col = i * 128 + lane * 4;
        float4 v4 = *reinterpret_cast<const float4*>(p + col);
        v[i * 4 + 0] = (col + 0 == r) ? -INFINITY : v4.x * scale;
        v[i * 4 + 1] = (col + 1 == r) ? -INFINITY : v4.y * scale;
        v[i * 4 + 2] = (col + 2 == r) ? -INFINITY : v4.z * scale;
        v[i * 4 + 3] = (col + 3 == r) ? -INFINITY : v4.w * scale;
#pragma unroll
        for (int j = 0; j < 4; j++) mx = fmaxf(mx, v[i * 4 + j]);
    }
#pragma unroll
    for (int o = 16; o; o >>= 1) mx = fmaxf(mx, __shfl_xor_sync(0xffffffffu, mx, o));

    float sum = 0.f;
#pragma unroll
    for (int i = 0; i < 16; i++) { v[i] = __expf(v[i] - mx); sum += v[i]; }
#pragma unroll
    for (int o = 16; o; o >>= 1) sum += __shfl_xor_sync(0xffffffffu, sum, o);
    const float inv = 1.f / sum;

#pragma unroll
    for (int i = 0; i < 4; i++) {
        const int col = i * 128 + lane * 4;
        *reinterpret_cast<__nv_bfloat162*>(q + col) =
            __floats2bfloat162_rn(v[i * 4 + 0] * inv, v[i * 4 + 1] * inv);
        *reinterpret_cast<__nv_bfloat162*>(q + col + 2) =
            __floats2bfloat162_rn(v[i * 4 + 2] * inv, v[i * 4 + 3] * inv);
    }
}

// ---------------------------------------------------------------------------
// Launcher. Inputs: x, batch(unused), Wq,bq, Wk,bk, Wv,bv, Wo,bo, beta.
// ---------------------------------------------------------------------------
extern "C" void kernel_launch(void* const* d_in, const int* in_sizes, int n_in,
                              void* d_out, int out_size)
{
    (void)in_sizes; (void)n_in; (void)out_size;
    const float* x    = (const float*)d_in[0];
    const float* Wq   = (const float*)d_in[2];
    const float* bq   = (const float*)d_in[3];
    const float* Wk   = (const float*)d_in[4];
    const float* bk   = (const float*)d_in[5];
    const float* Wv   = (const float*)d_in[6];
    const float* bv   = (const float*)d_in[7];
    const float* Wo   = (const float*)d_in[8];
    const float* bo   = (const float*)d_in[9];
    const float* beta = (const float*)d_in[10];
    float* out = (float*)d_out;

    __nv_bfloat16 *xb, *Wqb, *Wkb, *Wvb, *Wob, *Q, *K, *V, *P, *DYN;
    float *S;
    cudaGetSymbolAddress((void**)&xb,  g_xb);
    cudaGetSymbolAddress((void**)&Wqb, g_Wqb);
    cudaGetSymbolAddress((void**)&Wkb, g_Wkb);
    cudaGetSymbolAddress((void**)&Wvb, g_Wvb);
    cudaGetSymbolAddress((void**)&Wob, g_Wob);
    cudaGetSymbolAddress((void**)&Q,   g_Q);
    cudaGetSymbolAddress((void**)&K,   g_K);
    cudaGetSymbolAddress((void**)&V,   g_V);
    cudaGetSymbolAddress((void**)&S,   g_S);
    cudaGetSymbolAddress((void**)&P,   g_P);
    cudaGetSymbolAddress((void**)&DYN, g_DYN);

    static bool attr_done = false;
    if (!attr_done) {
        cudaFuncSetAttribute(hgemm_qkv,       cudaFuncAttributeMaxDynamicSharedMemorySize, SMEM_BYTES);
        cudaFuncSetAttribute(hgemm<1, false>, cudaFuncAttributeMaxDynamicSharedMemorySize, SMEM_BYTES);
        cudaFuncSetAttribute(hgemm<2, true>,  cudaFuncAttributeMaxDynamicSharedMemorySize, SMEM_BYTES);
        cudaFuncSetAttribute(hgemm<3, false>, cudaFuncAttributeMaxDynamicSharedMemorySize, SMEM_BYTES);
        attr_done = true;
    }

    const float scale = 1.0f / sqrtf((float)DIM);
    const dim3 blk(256);

    // converts (one launch)
    {
        long total4 = ((long)NG * DIM + 4L * DIM * DIM) / 4;
        int blocks = (int)((total4 + 255) / 256);
        conv_all<<<blocks, 256>>>(x, Wq, Wk, Wv, Wo, xb, Wqb, Wkb, Wvb, Wob);
    }

    // Q/K/V projections in one launch: bf16 [8192,768] @ [768,768]^T + bias
    hgemm_qkv<<<dim3(6, 64, 3), blk, SMEM_BYTES>>>(xb, Wqb, Wkb, Wvb, bq, bk, bv, Q, K, V);

    // Per-group scores: S_g = Q_g @ K_g^T (unscaled fp32, batched z=16)
    hgemm<1, false><<<dim3(4, 4, BGRP), blk, SMEM_BYTES>>>(
        Q, K, nullptr, S, DIM, DIM, DIM, GS,
        (long)GS * DIM, (long)GS * DIM, (long)GS * GS, nullptr, nullptr);

    // Masked softmax (scale folded): fp32 S -> bf16 P, warp-per-row
    softmax_rows<<<NG / 8, 256>>>(S, P, scale);

    // Per-group P @ V -> bf16 DYN (NN via ldmatrix.trans, batched z=16)
    hgemm<2, true><<<dim3(6, 4, BGRP), blk, SMEM_BYTES>>>(
        P, V, nullptr, DYN, GS, GS, DIM, DIM,
        (long)GS * GS, (long)GS * DIM, (long)GS * DIM, nullptr, nullptr);

    // Output projection + residual: out = x + beta*(DYN @ Wo^T + bo) (fp32)
    hgemm<3, false><<<dim3(6, 64, 1), blk, SMEM_BYTES>>>(
        DYN, Wob, bo, out, DIM, DIM, DIM, DIM, 0, 0, 0, x, beta);
}